// round 2
// baseline (speedup 1.0000x reference)
#include <cuda_runtime.h>

// out[t] = 0.5*x[t] + 0.4*x[t-11026] + 0.32*x[t-22051] + 0.256*x[t-33076] + 0.2048*x[t-44101]
// (taps read zero when index < 0)

#define S0 11026   // == 2 mod 4  -> 8B aligned from a 16B-aligned granule base
#define S1 22051   // == 1 mod 4  -> scalar
#define S2 33076   // == 0 mod 4  -> 16B aligned
#define S3 44101   // == 3 mod 4  -> scalar

#define G_DRY 0.5f
#define G0 0.4f
#define G1 0.32f
#define G2 0.256f
#define G3 0.2048f

__global__ __launch_bounds__(256) void mtd_kernel(const float* __restrict__ x,
                                                  float* __restrict__ out,
                                                  int n) {
    int t0 = (blockIdx.x * blockDim.x + threadIdx.x) * 4;
    if (t0 >= n) return;

    if (t0 >= S3 && t0 + 3 < n) {
        // Fast path: all taps in range, full float4 granule.
        float4 xv = *reinterpret_cast<const float4*>(x + t0);

        // Tap 2: 16B-aligned -> float4
        float4 v2 = *reinterpret_cast<const float4*>(x + (t0 - S2));

        // Tap 0: 8B-aligned -> two float2
        const float* p0 = x + (t0 - S0);
        float2 v0a = *reinterpret_cast<const float2*>(p0);
        float2 v0b = *reinterpret_cast<const float2*>(p0 + 2);

        // Taps 1, 3: unaligned -> scalar
        const float* p1 = x + (t0 - S1);
        const float* p3 = x + (t0 - S3);

        float r0 = G_DRY * xv.x + G0 * v0a.x + G1 * __ldg(p1 + 0) + G2 * v2.x + G3 * __ldg(p3 + 0);
        float r1 = G_DRY * xv.y + G0 * v0a.y + G1 * __ldg(p1 + 1) + G2 * v2.y + G3 * __ldg(p3 + 1);
        float r2 = G_DRY * xv.z + G0 * v0b.x + G1 * __ldg(p1 + 2) + G2 * v2.z + G3 * __ldg(p3 + 2);
        float r3 = G_DRY * xv.w + G0 * v0b.y + G1 * __ldg(p1 + 3) + G2 * v2.w + G3 * __ldg(p3 + 3);

        *reinterpret_cast<float4*>(out + t0) = make_float4(r0, r1, r2, r3);
    } else {
        // Slow path: boundary (t < S3) and/or array tail.
        #pragma unroll
        for (int j = 0; j < 4; j++) {
            int t = t0 + j;
            if (t >= n) break;
            float r = G_DRY * x[t];
            if (t >= S0) r += G0 * x[t - S0];
            if (t >= S1) r += G1 * x[t - S1];
            if (t >= S2) r += G2 * x[t - S2];
            if (t >= S3) r += G3 * x[t - S3];
            out[t] = r;
        }
    }
}

extern "C" void kernel_launch(void* const* d_in, const int* in_sizes, int n_in,
                              void* d_out, int out_size) {
    const float* x = (const float*)d_in[0];
    float* out = (float*)d_out;
    int n = in_sizes[0];

    int threads = 256;
    int granules = (n + 3) / 4;
    int blocks = (granules + threads - 1) / threads;
    mtd_kernel<<<blocks, threads>>>(x, out, n);
}

// round 3
// speedup vs baseline: 1.0207x; 1.0207x over previous
#include <cuda_runtime.h>

// out[t] = 0.5*x[t] + 0.4*x[t-11026] + 0.32*x[t-22051] + 0.256*x[t-33076] + 0.2048*x[t-44101]
// taps read zero when index < 0.
//
// Residues (t0 multiple of 4):  t0-S0 == 2 (mod 4), t0-S1 == 1, t0-S2 == 0, t0-S3 == 3.
// Each tap is read with ONE aligned LDG.128 per thread; the misaligned window is
// rebuilt via __shfl_down of the neighboring lane's granule (lane 31 patches with
// scalar __ldg). This minimizes L1 wavefronts (prev kernel was L1-bound at 91%).

#define S0 11026
#define S1 22051
#define S2 33076
#define S3 44101

#define G_DRY 0.5f
#define G0 0.4f
#define G1 0.32f
#define G2 0.256f
#define G3 0.2048f

// Load the 4 words x[a+R .. a+R+3] where a is 16B-aligned (a = t0 - S - R).
// Warp-collective (uses shuffles): only call on a warp-uniform fast path.
template <int R>
__device__ __forceinline__ float4 load_shifted(const float* __restrict__ x, int a, int lane) {
    float4 F = *reinterpret_cast<const float4*>(x + a);
    if (R == 0) return F;

    float g0 = 0.f, g1 = 0.f, g2 = 0.f;
    if (R >= 1) g0 = __shfl_down_sync(0xffffffffu, F.x, 1);
    if (R >= 2) g1 = __shfl_down_sync(0xffffffffu, F.y, 1);
    if (R >= 3) g2 = __shfl_down_sync(0xffffffffu, F.z, 1);
    if (lane == 31) {
        // Next granule belongs to the next warp; fetch the few missing words.
        if (R >= 1) g0 = __ldg(x + a + 4);
        if (R >= 2) g1 = __ldg(x + a + 5);
        if (R >= 3) g2 = __ldg(x + a + 6);
    }
    if (R == 1) return make_float4(F.y, F.z, F.w, g0);
    if (R == 2) return make_float4(F.z, F.w, g0, g1);
    /* R == 3 */ return make_float4(F.w, g0, g1, g2);
}

__global__ __launch_bounds__(256) void mtd_kernel(const float* __restrict__ x,
                                                  float* __restrict__ out,
                                                  int n) {
    int tid = blockIdx.x * blockDim.x + threadIdx.x;
    int t0 = tid * 4;
    int lane = threadIdx.x & 31;

    // Warp-uniform fast-path condition: every lane's deepest aligned base >= 0
    // and every lane's last output index < n.
    int warp_t0 = (tid & ~31) * 4;              // first lane's t0 (uniform in warp)
    bool fast = (warp_t0 >= S3 + 3) && (warp_t0 + 127 < n);

    if (fast) {
        float4 xv = *reinterpret_cast<const float4*>(x + t0);
        float4 v0 = load_shifted<2>(x, t0 - S0 - 2, lane);
        float4 v1 = load_shifted<1>(x, t0 - S1 - 1, lane);
        float4 v2 = load_shifted<0>(x, t0 - S2 - 0, lane);
        float4 v3 = load_shifted<3>(x, t0 - S3 - 3, lane);

        float r0 = G_DRY * xv.x + G0 * v0.x + G1 * v1.x + G2 * v2.x + G3 * v3.x;
        float r1 = G_DRY * xv.y + G0 * v0.y + G1 * v1.y + G2 * v2.y + G3 * v3.y;
        float r2 = G_DRY * xv.z + G0 * v0.z + G1 * v1.z + G2 * v2.z + G3 * v3.z;
        float r3 = G_DRY * xv.w + G0 * v0.w + G1 * v1.w + G2 * v2.w + G3 * v3.w;

        *reinterpret_cast<float4*>(out + t0) = make_float4(r0, r1, r2, r3);
    } else {
        // Boundary (t < S3+ε) and/or array tail: per-element predicated path.
        #pragma unroll
        for (int j = 0; j < 4; j++) {
            int t = t0 + j;
            if (t >= n) break;
            float r = G_DRY * x[t];
            if (t >= S0) r += G0 * x[t - S0];
            if (t >= S1) r += G1 * x[t - S1];
            if (t >= S2) r += G2 * x[t - S2];
            if (t >= S3) r += G3 * x[t - S3];
            out[t] = r;
        }
    }
}

extern "C" void kernel_launch(void* const* d_in, const int* in_sizes, int n_in,
                              void* d_out, int out_size) {
    const float* x = (const float*)d_in[0];
    float* out = (float*)d_out;
    int n = in_sizes[0];

    int threads = 256;
    int granules = (n + 3) / 4;
    int blocks = (granules + threads - 1) / threads;
    mtd_kernel<<<blocks, threads>>>(x, out, n);
}